// round 4
// baseline (speedup 1.0000x reference)
#include <cuda_runtime.h>
#include <cuda_fp16.h>
#include <mma.h>
#include <math.h>

using namespace nvcuda;

#define N_NODES   50000
#define N_PAD     50048          // 391 * 128
#define N_EDGES   800000
#define HIDDEN    128
#define NUM_GRAPHS 256
#define PF 4

// ---------------- scratch (device globals) ----------------------------------
__device__ float  g_h[N_NODES * HIDDEN];
__device__ float  g_agg[N_NODES * HIDDEN];
__device__ __half g_A[(size_t)N_PAD * 512];     // packed projections fp16 (51 MB)
__device__ __half g_WW[128 * 512];              // node GEMM weight fp16
__device__ __half g_WT[256 * 32];               // edge gate W^T fp16 (gate-interleaved)
__device__ float  g_gsum[NUM_GRAPHS * HIDDEN];
__device__ float  g_gcnt[NUM_GRAPHS];

// ---------------- conv1: CGConv(C=3, edge=32) -------------------------------
__global__ __launch_bounds__(256) void conv1_kernel(
    const float* __restrict__ x, const int* __restrict__ src, const int* __restrict__ dst,
    const float* __restrict__ eattr,
    const float* __restrict__ Wf, const float* __restrict__ bf,
    const float* __restrict__ Ws, const float* __restrict__ bs,
    float* __restrict__ agg)
{
    __shared__ float wf[38 * 3], ws[38 * 3], bfs[3], bss[3];
    int tid = threadIdx.x;
    if (tid < 114) { wf[tid] = Wf[tid]; ws[tid] = Ws[tid]; }
    if (tid < 3)   { bfs[tid] = bf[tid]; bss[tid] = bs[tid]; }
    __syncthreads();

    int e = blockIdx.x * 256 + tid;
    int d  = dst[e];
    int sn = src[e];

    float f[3], s[3];
#pragma unroll
    for (int j = 0; j < 3; j++) { f[j] = bfs[j]; s[j] = bss[j]; }

#pragma unroll
    for (int i = 0; i < 3; i++) {
        float xd = x[d * 3 + i];
        float xs = x[sn * 3 + i];
#pragma unroll
        for (int j = 0; j < 3; j++) {
            f[j] += xd * wf[i * 3 + j];
            s[j] += xd * ws[i * 3 + j];
            f[j] += xs * wf[(3 + i) * 3 + j];
            s[j] += xs * ws[(3 + i) * 3 + j];
        }
    }
    const float4* ep = (const float4*)(eattr + (size_t)e * 32);
#pragma unroll
    for (int q = 0; q < 8; q++) {
        float4 v = ep[q];
        float ev[4] = {v.x, v.y, v.z, v.w};
#pragma unroll
        for (int r = 0; r < 4; r++) {
            int k = 6 + q * 4 + r;
#pragma unroll
            for (int j = 0; j < 3; j++) {
                f[j] += ev[r] * wf[k * 3 + j];
                s[j] += ev[r] * ws[k * 3 + j];
            }
        }
    }
#pragma unroll
    for (int j = 0; j < 3; j++) {
        float sg = __fdividef(1.f, 1.f + __expf(-f[j]));
        float sp = fmaxf(s[j], 0.f) + __logf(1.f + __expf(-fabsf(s[j])));
        atomicAdd(agg + (size_t)d * 3 + j, sg * sp);
    }
}

// ---------------- node projection -------------------------------------------
__global__ __launch_bounds__(256) void proj_kernel(
    const float* __restrict__ x, const float* __restrict__ agg1,
    const float* __restrict__ Wp, const float* __restrict__ bp,
    float* __restrict__ h)
{
    int idx = blockIdx.x * 256 + threadIdx.x;
    int n = idx >> 7, c = idx & 127;
    float v = bp[c];
#pragma unroll
    for (int i = 0; i < 3; i++)
        v += (x[n * 3 + i] + agg1[n * 3 + i]) * Wp[i * 128 + c];
    h[idx] = fmaxf(v, 0.f);
}

// ---------------- weight pack: WW fp16 [128][512], WT fp16 [256][32] ---------
__global__ __launch_bounds__(256) void pack_kernel(
    const float* __restrict__ Wf, const float* __restrict__ Ws,
    __half* __restrict__ WW, __half* __restrict__ WT)
{
    int idx = blockIdx.x * 256 + threadIdx.x;   // 0 .. 128*512-1
    {
        int k = idx >> 9;
        int j = idx & 511;
        int role = j >> 8;
        int c = (j & 255) >> 1;
        int gate = j & 1;
        const float* G = gate ? Ws : Wf;
        WW[idx] = __float2half(G[(role * 128 + k) * 128 + c]);
    }
    if (idx < 256 * 32) {
        int g = idx >> 5;
        int k = idx & 31;
        int c = g >> 1;
        int gate = g & 1;
        const float* G = gate ? Ws : Wf;
        WT[idx] = __float2half(G[(256 + k) * 128 + c]);
    }
}

// ---------------- node GEMM via wmma: A[N_PAD,512](fp16) = h @ WW -------------
__global__ __launch_bounds__(256) void gemm_node(
    const float* __restrict__ H, const __half* __restrict__ WW, __half* __restrict__ A)
{
    extern __shared__ char sm[];
    __half (*hs)[128] = (__half(*)[128])sm;                 // 32 KB
    __half (*ws)[128] = (__half(*)[128])(sm + 32768);       // 32 KB

    int tid = threadIdx.x;
    int w   = tid >> 5;
    int bm  = blockIdx.x * 128;
    int bn  = blockIdx.y * 128;

    // stage H tile (fp32 -> fp16)
#pragma unroll
    for (int t = 0; t < 16; t++) {
        int li  = tid + t * 256;       // 0..4095 float4
        int row = li >> 5, q = li & 31;
        int r = bm + row; if (r > N_NODES - 1) r = N_NODES - 1;
        float4 v = *(const float4*)(H + (size_t)r * 128 + q * 4);
        __half2* dp = (__half2*)&hs[row][q * 4];
        dp[0] = __floats2half2_rn(v.x, v.y);
        dp[1] = __floats2half2_rn(v.z, v.w);
    }
    // stage W tile
#pragma unroll
    for (int t = 0; t < 8; t++) {
        int li  = tid + t * 256;       // 0..2047 uint4
        int row = li >> 4, q8 = li & 15;
        *(uint4*)&ws[row][q8 * 8] = *(const uint4*)(WW + (size_t)row * 512 + bn + q8 * 8);
    }
    __syncthreads();

    wmma::fragment<wmma::matrix_a, 16, 16, 16, __half, wmma::row_major> a[8];
#pragma unroll
    for (int k = 0; k < 8; k++)
        wmma::load_matrix_sync(a[k], &hs[w * 16][k * 16], 128);

#pragma unroll
    for (int nt = 0; nt < 8; nt++) {
        wmma::fragment<wmma::accumulator, 16, 16, 16, float> acc;
        wmma::fill_fragment(acc, 0.f);
#pragma unroll
        for (int k = 0; k < 8; k++) {
            wmma::fragment<wmma::matrix_b, 16, 16, 16, __half, wmma::row_major> b;
            wmma::load_matrix_sync(b, &ws[k * 16][nt * 16], 128);
            wmma::mma_sync(acc, a[k], b, acc);
        }
        wmma::fragment<wmma::accumulator, 16, 16, 16, __half> hacc;
#pragma unroll
        for (int i = 0; i < acc.num_elements; i++) hacc.x[i] = __float2half(acc.x[i]);
        wmma::store_matrix_sync(A + (size_t)(bm + w * 16) * 512 + bn + nt * 16,
                                hacc, 512, wmma::mem_row_major);
    }
}

// ---------------- fused CGConv edge kernel (wmma gate GEMM + activation) -----
__global__ __launch_bounds__(256, 2) void edge_kernel(
    const int* __restrict__ src, const int* __restrict__ dst,
    const float* __restrict__ eattr,
    const __half* __restrict__ WT,
    const float* __restrict__ bf, const float* __restrict__ bs,
    const __half2* __restrict__ A2, float* __restrict__ agg)
{
    extern __shared__ char sm[];
    __half (*Es)[32]   = (__half(*)[32])sm;                        // 8 KB
    __half (*WTs)[32]  = (__half(*)[32])(sm + 8192);               // 16 KB
    __half (*Ew)[256]  = (__half(*)[256])(sm + 8192 + 16384);      // 64 KB
    int2*  di          = (int2*)(sm + 8192 + 16384 + 65536);       // 1 KB

    int tid = threadIdx.x;
    int w   = tid >> 5;
    int ebase = blockIdx.x * 128;

    if (tid < 128) di[tid] = make_int2(dst[ebase + tid], src[ebase + tid]);
    {
        const float4* b4 = (const float4*)(eattr + (size_t)ebase * 32);
#pragma unroll
        for (int t = 0; t < 4; t++) {
            int li = tid + t * 256;        // 0..1023
            float4 v = __ldcs(b4 + li);
            int e = li >> 3, q = li & 7;
            __half2* dp = (__half2*)&Es[e][q * 4];
            dp[0] = __floats2half2_rn(v.x, v.y);
            dp[1] = __floats2half2_rn(v.z, v.w);
        }
    }
    {
        const uint4* wsrc = (const uint4*)WT;
        uint4* wdst = (uint4*)WTs;
#pragma unroll
        for (int t = 0; t < 4; t++)
            wdst[tid + t * 256] = wsrc[tid + t * 256];
    }
    __syncthreads();

    // phase 1: Ew[128 edges][256 gates] = Es @ WT^T   (gates interleaved f,s)
    {
        wmma::fragment<wmma::matrix_a, 16, 16, 16, __half, wmma::row_major> a0, a1;
        wmma::load_matrix_sync(a0, &Es[w * 16][0], 32);
        wmma::load_matrix_sync(a1, &Es[w * 16][16], 32);
#pragma unroll
        for (int nt = 0; nt < 16; nt++) {
            wmma::fragment<wmma::accumulator, 16, 16, 16, float> acc;
            wmma::fill_fragment(acc, 0.f);
            wmma::fragment<wmma::matrix_b, 16, 16, 16, __half, wmma::col_major> b0, b1;
            wmma::load_matrix_sync(b0, &WTs[nt * 16][0], 32);
            wmma::load_matrix_sync(b1, &WTs[nt * 16][16], 32);
            wmma::mma_sync(acc, a0, b0, acc);
            wmma::mma_sync(acc, a1, b1, acc);
            wmma::fragment<wmma::accumulator, 16, 16, 16, __half> hacc;
#pragma unroll
            for (int i = 0; i < acc.num_elements; i++) hacc.x[i] = __float2half(acc.x[i]);
            wmma::store_matrix_sync(&Ew[w * 16][nt * 16], hacc, 256, wmma::mem_row_major);
        }
    }
    __syncthreads();

    // phase 2: gather + activation + scatter
    int c   = tid & 127;
    int grp = tid >> 7;
    float bfc = __ldg(&bf[c]), bsc = __ldg(&bs[c]);
    int e0 = grp * 64;

    __half2 pvd[PF], pvs[PF];
#pragma unroll
    for (int i = 0; i < PF; i++) {
        int2 ds = di[e0 + i];
        pvd[i] = __ldg(A2 + (size_t)ds.x * 256 + c);
        pvs[i] = __ldg(A2 + (size_t)ds.y * 256 + 128 + c);
    }

#pragma unroll 4
    for (int i = 0; i < 64; i++) {
        __half2 vd = pvd[i & (PF - 1)];
        __half2 vs = pvs[i & (PF - 1)];
        if (i + PF < 64) {
            int2 ds = di[e0 + i + PF];
            pvd[i & (PF - 1)] = __ldg(A2 + (size_t)ds.x * 256 + c);
            pvs[i & (PF - 1)] = __ldg(A2 + (size_t)ds.y * 256 + 128 + c);
        }
        __half2 ew = *(__half2*)&Ew[e0 + i][2 * c];
        float2 fe = __half22float2(ew);
        float2 fd = __half22float2(vd);
        float2 fv = __half22float2(vs);
        float f = bfc + fd.x + fv.x + fe.x;
        float s = bsc + fd.y + fv.y + fe.y;
        float sg = __fdividef(1.f, 1.f + __expf(-f));
        float sp = fmaxf(s, 0.f) + __logf(1.f + __expf(-fabsf(s)));
        atomicAdd(agg + (size_t)di[e0 + i].x * 128 + c, sg * sp);
    }
}

// ---------------- h = relu(h + agg) ------------------------------------------
__global__ __launch_bounds__(256) void relu_add_kernel(float* __restrict__ h, const float* __restrict__ agg)
{
    int idx = blockIdx.x * 256 + threadIdx.x;
    h[idx] = fmaxf(h[idx] + agg[idx], 0.f);
}

// ---------------- final relu + mean pool fused --------------------------------
__global__ __launch_bounds__(256) void relu_pool_kernel(
    const float* __restrict__ h, const float* __restrict__ agg,
    const int* __restrict__ batch,
    float* __restrict__ gsum, float* __restrict__ gcnt)
{
    int idx = blockIdx.x * 256 + threadIdx.x;
    int n = idx >> 7, c = idx & 127;
    float v = fmaxf(h[idx] + agg[idx], 0.f);
    int b = batch[n];
    atomicAdd(gsum + (size_t)b * 128 + c, v);
    if (c == 0) atomicAdd(gcnt + b, 1.f);
}

// ---------------- final MLP ---------------------------------------------------
__global__ __launch_bounds__(128) void final_kernel(
    const float* __restrict__ gsum, const float* __restrict__ gcnt,
    const float* __restrict__ W1, const float* __restrict__ b1,
    const float* __restrict__ Wh, const float* __restrict__ bh,
    float* __restrict__ out)
{
    __shared__ float mean[128];
    __shared__ float ga[128];
    int g = blockIdx.x;
    int c = threadIdx.x;
    float cnt = fmaxf(gcnt[g], 1.f);
    mean[c] = gsum[(size_t)g * 128 + c] / cnt;
    __syncthreads();
    float acc = b1[c];
#pragma unroll 8
    for (int k = 0; k < 128; k++)
        acc += mean[k] * W1[k * 128 + c];
    ga[c] = fmaxf(acc, 0.f);
    __syncthreads();
    if (c < 5) {
        float o = bh[c];
#pragma unroll 8
        for (int k = 0; k < 128; k++)
            o += ga[k] * Wh[c * 128 + k];
        out[g * 5 + c] = o;
    }
}

// =============================================================================
extern "C" void kernel_launch(void* const* d_in, const int* in_sizes, int n_in,
                              void* d_out, int out_size)
{
    const float* x        = (const float*)d_in[0];
    const int*   eidx     = (const int*)  d_in[1];
    const float* eattr    = (const float*)d_in[2];
    const int*   batch    = (const int*)  d_in[3];
    const float* Wf1      = (const float*)d_in[4];
    const float* bf1      = (const float*)d_in[5];
    const float* Ws1      = (const float*)d_in[6];
    const float* bs1      = (const float*)d_in[7];
    const float* Wp       = (const float*)d_in[8];
    const float* bp       = (const float*)d_in[9];
    const float* Wf_convs = (const float*)d_in[10];
    const float* bf_convs = (const float*)d_in[11];
    const float* Ws_convs = (const float*)d_in[12];
    const float* bs_convs = (const float*)d_in[13];
    const float* W1       = (const float*)d_in[14];
    const float* b1       = (const float*)d_in[15];
    const float* Wh       = (const float*)d_in[16];
    const float* bh       = (const float*)d_in[17];
    float* out = (float*)d_out;

    const int* srcp = eidx;
    const int* dstp = eidx + N_EDGES;

    float *p_h, *p_agg, *p_gsum, *p_gcnt;
    __half *p_A, *p_WW, *p_WT;
    cudaGetSymbolAddress((void**)&p_h,    g_h);
    cudaGetSymbolAddress((void**)&p_agg,  g_agg);
    cudaGetSymbolAddress((void**)&p_A,    g_A);
    cudaGetSymbolAddress((void**)&p_WW,   g_WW);
    cudaGetSymbolAddress((void**)&p_WT,   g_WT);
    cudaGetSymbolAddress((void**)&p_gsum, g_gsum);
    cudaGetSymbolAddress((void**)&p_gcnt, g_gcnt);

    static int smem_cfg = 0;
    if (!smem_cfg) {
        cudaFuncSetAttribute(gemm_node, cudaFuncAttributeMaxDynamicSharedMemorySize, 65536);
        cudaFuncSetAttribute(edge_kernel, cudaFuncAttributeMaxDynamicSharedMemorySize, 91136);
        smem_cfg = 1;
    }

    const int EB  = N_EDGES / 256;                    // 3125 (conv1)
    const int EB2 = N_EDGES / 128;                    // 6250 (fused edge)
    const int NB  = (N_NODES * HIDDEN) / 256;         // 25000

    // conv1
    cudaMemsetAsync(p_agg, 0, (size_t)N_NODES * 3 * sizeof(float));
    conv1_kernel<<<EB, 256>>>(x, srcp, dstp, eattr, Wf1, bf1, Ws1, bs1, p_agg);
    proj_kernel<<<NB, 256>>>(x, p_agg, Wp, bp, p_h);

    cudaMemsetAsync(p_gsum, 0, (size_t)NUM_GRAPHS * HIDDEN * sizeof(float));
    cudaMemsetAsync(p_gcnt, 0, (size_t)NUM_GRAPHS * sizeof(float));

    // two big CGConv layers
    for (int l = 0; l < 2; l++) {
        const float* Wf = Wf_convs + (size_t)l * 288 * 128;
        const float* Ws = Ws_convs + (size_t)l * 288 * 128;
        const float* bf = bf_convs + (size_t)l * 128;
        const float* bs = bs_convs + (size_t)l * 128;

        pack_kernel<<<(128 * 512) / 256, 256>>>(Wf, Ws, p_WW, p_WT);
        dim3 gg(N_PAD / 128, 4);
        gemm_node<<<gg, 256, 65536>>>(p_h, p_WW, p_A);
        cudaMemsetAsync(p_agg, 0, (size_t)N_NODES * HIDDEN * sizeof(float));
        edge_kernel<<<EB2, 256, 91136>>>(srcp, dstp, eattr, p_WT, bf, bs,
                                         (const __half2*)p_A, p_agg);
        if (l == 0)
            relu_add_kernel<<<NB, 256>>>(p_h, p_agg);
        else
            relu_pool_kernel<<<NB, 256>>>(p_h, p_agg, batch, p_gsum, p_gcnt);
    }

    final_kernel<<<NUM_GRAPHS, 128>>>(p_gsum, p_gcnt, W1, b1, Wh, bh, out);
}

// round 5
// speedup vs baseline: 1.2986x; 1.2986x over previous
#include <cuda_runtime.h>
#include <cuda_fp16.h>
#include <mma.h>
#include <math.h>

using namespace nvcuda;

#define N_NODES   50000
#define N_EDGES   800000
#define HIDDEN    128
#define NUM_GRAPHS 256

// ---------------- scratch (device globals) ----------------------------------
__device__ float  g_h[N_NODES * HIDDEN];
__device__ float  g_agg[N_NODES * HIDDEN];
__device__ __half g_A[(size_t)N_NODES * 512];   // packed projections fp16 (51 MB)
__device__ float  g_WW[128 * 512];              // node GEMM weight fp32 (packed)
__device__ __half g_WT[256 * 32];               // edge gate W^T fp16 (gate-interleaved)
__device__ float  g_gsum[NUM_GRAPHS * HIDDEN];
__device__ float  g_gcnt[NUM_GRAPHS];

// ---------------- f32x2 helpers ----------------------------------------------
__device__ __forceinline__ unsigned long long mk2(float lo, float hi) {
    unsigned long long r; asm("mov.b64 %0, {%1, %2};" : "=l"(r) : "f"(lo), "f"(hi)); return r;
}
__device__ __forceinline__ unsigned long long dup2(float x) {
    unsigned long long r; asm("mov.b64 %0, {%1, %1};" : "=l"(r) : "f"(x)); return r;
}
__device__ __forceinline__ void fma2(unsigned long long &d, unsigned long long a, unsigned long long b) {
    asm("fma.rn.f32x2 %0, %1, %2, %3;" : "=l"(d) : "l"(a), "l"(b), "l"(d));
}
__device__ __forceinline__ float2 unpk(unsigned long long v) {
    float2 r; asm("mov.b64 {%0, %1}, %2;" : "=f"(r.x), "=f"(r.y) : "l"(v)); return r;
}
__device__ __forceinline__ void red_v4(float* p, float a, float b, float c, float d) {
    asm volatile("red.global.add.v4.f32 [%0], {%1,%2,%3,%4};"
                 :: "l"(p), "f"(a), "f"(b), "f"(c), "f"(d) : "memory");
}

// ---------------- conv1: CGConv(C=3, edge=32) -------------------------------
__global__ __launch_bounds__(256) void conv1_kernel(
    const float* __restrict__ x, const int* __restrict__ src, const int* __restrict__ dst,
    const float* __restrict__ eattr,
    const float* __restrict__ Wf, const float* __restrict__ bf,
    const float* __restrict__ Ws, const float* __restrict__ bs,
    float* __restrict__ agg)
{
    __shared__ float wf[38 * 3], ws[38 * 3], bfs[3], bss[3];
    int tid = threadIdx.x;
    if (tid < 114) { wf[tid] = Wf[tid]; ws[tid] = Ws[tid]; }
    if (tid < 3)   { bfs[tid] = bf[tid]; bss[tid] = bs[tid]; }
    __syncthreads();

    int e = blockIdx.x * 256 + tid;
    int d  = dst[e];
    int sn = src[e];

    float f[3], s[3];
#pragma unroll
    for (int j = 0; j < 3; j++) { f[j] = bfs[j]; s[j] = bss[j]; }

#pragma unroll
    for (int i = 0; i < 3; i++) {
        float xd = x[d * 3 + i];
        float xs = x[sn * 3 + i];
#pragma unroll
        for (int j = 0; j < 3; j++) {
            f[j] += xd * wf[i * 3 + j];
            s[j] += xd * ws[i * 3 + j];
            f[j] += xs * wf[(3 + i) * 3 + j];
            s[j] += xs * ws[(3 + i) * 3 + j];
        }
    }
    const float4* ep = (const float4*)(eattr + (size_t)e * 32);
#pragma unroll
    for (int q = 0; q < 8; q++) {
        float4 v = ep[q];
        float ev[4] = {v.x, v.y, v.z, v.w};
#pragma unroll
        for (int r = 0; r < 4; r++) {
            int k = 6 + q * 4 + r;
#pragma unroll
            for (int j = 0; j < 3; j++) {
                f[j] += ev[r] * wf[k * 3 + j];
                s[j] += ev[r] * ws[k * 3 + j];
            }
        }
    }
#pragma unroll
    for (int j = 0; j < 3; j++) {
        float sg = __fdividef(1.f, 1.f + __expf(-f[j]));
        float sp = fmaxf(s[j], 0.f) + __logf(1.f + __expf(-fabsf(s[j])));
        atomicAdd(agg + (size_t)d * 3 + j, sg * sp);
    }
}

// ---------------- node projection -------------------------------------------
__global__ __launch_bounds__(256) void proj_kernel(
    const float* __restrict__ x, const float* __restrict__ agg1,
    const float* __restrict__ Wp, const float* __restrict__ bp,
    float* __restrict__ h)
{
    int idx = blockIdx.x * 256 + threadIdx.x;
    int n = idx >> 7, c = idx & 127;
    float v = bp[c];
#pragma unroll
    for (int i = 0; i < 3; i++)
        v += (x[n * 3 + i] + agg1[n * 3 + i]) * Wp[i * 128 + c];
    h[idx] = fmaxf(v, 0.f);
}

// ---------------- weight pack: WW fp32 [128][512], WT fp16 [256][32] ---------
__global__ __launch_bounds__(256) void pack_kernel(
    const float* __restrict__ Wf, const float* __restrict__ Ws,
    float* __restrict__ WW, __half* __restrict__ WT)
{
    int idx = blockIdx.x * 256 + threadIdx.x;   // 0 .. 128*512-1
    {
        int k = idx >> 9;
        int j = idx & 511;
        int role = j >> 8;
        int c = (j & 255) >> 1;
        int gate = j & 1;
        const float* G = gate ? Ws : Wf;
        WW[idx] = G[(role * 128 + k) * 128 + c];
    }
    if (idx < 256 * 32) {
        int g = idx >> 5;
        int k = idx & 31;
        int c = g >> 1;
        int gate = g & 1;
        const float* G = gate ? Ws : Wf;
        WT[idx] = __float2half(G[(256 + k) * 128 + c]);
    }
}

// ---------------- node GEMM (fp32 f32x2): A[*,512](fp16) = h @ WW ------------
__global__ __launch_bounds__(256) void gemm_node(
    const float* __restrict__ H, const float* __restrict__ W, __half* __restrict__ A)
{
    __shared__ float hs[16][132];
    __shared__ float ws[16][128];
    int bm = blockIdx.x * 128;
    int bn = blockIdx.y * 128;
    int tid = threadIdx.x;
    int tm = (tid >> 4) * 8;
    int tn = (tid & 15) * 8;
    unsigned long long acc2[8][4];
#pragma unroll
    for (int i = 0; i < 8; i++)
#pragma unroll
        for (int j = 0; j < 4; j++) acc2[i][j] = 0ULL;

    for (int k0 = 0; k0 < 128; k0 += 16) {
#pragma unroll
        for (int t = 0; t < 2; t++) {
            int li = tid + t * 256;
            int m  = li >> 2;
            int kq = li & 3;
            int row = bm + m; if (row >= N_NODES) row = N_NODES - 1;
            float4 v = *(const float4*)(H + (size_t)row * 128 + k0 + kq * 4);
            hs[kq * 4 + 0][m] = v.x;
            hs[kq * 4 + 1][m] = v.y;
            hs[kq * 4 + 2][m] = v.z;
            hs[kq * 4 + 3][m] = v.w;
        }
#pragma unroll
        for (int t = 0; t < 2; t++) {
            int li = tid + t * 256;
            int k  = li >> 5;
            int cq = li & 31;
            float4 v = *(const float4*)(W + (size_t)(k0 + k) * 512 + bn + cq * 4);
            *(float4*)&ws[k][cq * 4] = v;
        }
        __syncthreads();
#pragma unroll
        for (int k = 0; k < 16; k++) {
            float4 a0 = *(float4*)&hs[k][tm];
            float4 a1 = *(float4*)&hs[k][tm + 4];
            float4 w0 = *(float4*)&ws[k][tn];
            float4 w1 = *(float4*)&ws[k][tn + 4];
            unsigned long long wp0 = mk2(w0.x, w0.y);
            unsigned long long wp1 = mk2(w0.z, w0.w);
            unsigned long long wp2 = mk2(w1.x, w1.y);
            unsigned long long wp3 = mk2(w1.z, w1.w);
            float am[8] = {a0.x, a0.y, a0.z, a0.w, a1.x, a1.y, a1.z, a1.w};
#pragma unroll
            for (int i = 0; i < 8; i++) {
                unsigned long long ad = dup2(am[i]);
                fma2(acc2[i][0], ad, wp0);
                fma2(acc2[i][1], ad, wp1);
                fma2(acc2[i][2], ad, wp2);
                fma2(acc2[i][3], ad, wp3);
            }
        }
        __syncthreads();
    }
#pragma unroll
    for (int i = 0; i < 8; i++) {
        int row = bm + tm + i;
        if (row < N_NODES) {
            uint4 o;
            unsigned* op = (unsigned*)&o;
#pragma unroll
            for (int p = 0; p < 4; p++) {
                float2 fp = unpk(acc2[i][p]);
                __half2 hp = __floats2half2_rn(fp.x, fp.y);
                op[p] = *(unsigned*)&hp;
            }
            *(uint4*)(A + (size_t)row * 512 + bn + tn) = o;
        }
    }
}

// ---------------- fused CGConv edge kernel (64 edges/block) ------------------
// smem: Es 4KB + WTs 16KB + Ew 32KB + di 0.5KB = 52.5KB -> 4 blocks/SM
__global__ __launch_bounds__(256) void edge_kernel(
    const int* __restrict__ src, const int* __restrict__ dst,
    const float* __restrict__ eattr,
    const __half* __restrict__ WT,
    const float* __restrict__ bf, const float* __restrict__ bs,
    const uint4* __restrict__ A4, float* __restrict__ agg)
{
    extern __shared__ char sm[];
    __half (*Es)[32]   = (__half(*)[32])sm;                        // 4 KB
    __half (*WTs)[32]  = (__half(*)[32])(sm + 4096);               // 16 KB
    __half (*Ew)[256]  = (__half(*)[256])(sm + 4096 + 16384);      // 32 KB
    int2*  di          = (int2*)(sm + 4096 + 16384 + 32768);       // 512 B

    int tid = threadIdx.x;
    int w   = tid >> 5;
    int l   = tid & 31;
    int ebase = blockIdx.x * 64;

    if (tid < 64) di[tid] = make_int2(dst[ebase + tid], src[ebase + tid]);
    {   // edge attrs -> fp16 smem (streaming)
        const float4* b4 = (const float4*)(eattr + (size_t)ebase * 32);
#pragma unroll
        for (int t = 0; t < 2; t++) {
            int li = tid + t * 256;        // 0..511
            float4 v = __ldcs(b4 + li);
            int e = li >> 3, q = li & 7;
            __half2* dp = (__half2*)&Es[e][q * 4];
            dp[0] = __floats2half2_rn(v.x, v.y);
            dp[1] = __floats2half2_rn(v.z, v.w);
        }
    }
    {   // gate weights
        const uint4* wsrc = (const uint4*)WT;
        uint4* wdst = (uint4*)WTs;
#pragma unroll
        for (int t = 0; t < 4; t++)
            wdst[tid + t * 256] = wsrc[tid + t * 256];
    }
    __syncthreads();

    // phase 1: Ew[64][256] = Es @ WT^T  (wmma, fp32 accum)
    {
        int mt = w & 3;
        int nb = (w >> 2) * 8;
        wmma::fragment<wmma::matrix_a, 16, 16, 16, __half, wmma::row_major> a0, a1;
        wmma::load_matrix_sync(a0, &Es[mt * 16][0], 32);
        wmma::load_matrix_sync(a1, &Es[mt * 16][16], 32);
#pragma unroll
        for (int t = 0; t < 8; t++) {
            int nt = nb + t;
            wmma::fragment<wmma::accumulator, 16, 16, 16, float> acc;
            wmma::fill_fragment(acc, 0.f);
            wmma::fragment<wmma::matrix_b, 16, 16, 16, __half, wmma::col_major> b0, b1;
            wmma::load_matrix_sync(b0, &WTs[nt * 16][0], 32);
            wmma::load_matrix_sync(b1, &WTs[nt * 16][16], 32);
            wmma::mma_sync(acc, a0, b0, acc);
            wmma::mma_sync(acc, a1, b1, acc);
            wmma::fragment<wmma::accumulator, 16, 16, 16, __half> hacc;
#pragma unroll
            for (int i = 0; i < acc.num_elements; i++) hacc.x[i] = __float2half(acc.x[i]);
            wmma::store_matrix_sync(&Ew[mt * 16][nt * 16], hacc, 256, wmma::mem_row_major);
        }
    }
    __syncthreads();

    // phase 2: warp-per-edge, lane l owns channels 4l..4l+3, vector RED
    float4 bf4 = *(const float4*)(bf + 4 * l);
    float4 bs4 = *(const float4*)(bs + 4 * l);
    int e0 = w * 8;

    int2  dsbuf[2];
    uint4 pd[2], ps[2];
    dsbuf[0] = di[e0];
    pd[0] = __ldg(A4 + (size_t)dsbuf[0].x * 64 + l);
    ps[0] = __ldg(A4 + (size_t)dsbuf[0].y * 64 + 32 + l);

#pragma unroll
    for (int i = 0; i < 8; i++) {
        int cur = i & 1, nxt = cur ^ 1;
        if (i < 7) {
            dsbuf[nxt] = di[e0 + i + 1];
            pd[nxt] = __ldg(A4 + (size_t)dsbuf[nxt].x * 64 + l);
            ps[nxt] = __ldg(A4 + (size_t)dsbuf[nxt].y * 64 + 32 + l);
        }
        uint4 ewv = *(uint4*)&Ew[e0 + i][8 * l];
        uint4 rd = pd[cur], rs = ps[cur];
        const __half2* hd = (const __half2*)&rd;
        const __half2* hsv = (const __half2*)&rs;
        const __half2* he = (const __half2*)&ewv;
        const float* bfp = (const float*)&bf4;
        const float* bsp = (const float*)&bs4;
        float msg[4];
#pragma unroll
        for (int j = 0; j < 4; j++) {
            float2 fd = __half22float2(hd[j]);
            float2 fv = __half22float2(hsv[j]);
            float2 fe = __half22float2(he[j]);
            float f = bfp[j] + fd.x + fv.x + fe.x;
            float s = bsp[j] + fd.y + fv.y + fe.y;
            float sg = __fdividef(1.f, 1.f + __expf(-f));
            float sp = fmaxf(s, 0.f) + __logf(1.f + __expf(-fabsf(s)));
            msg[j] = sg * sp;
        }
        red_v4(agg + (size_t)dsbuf[cur].x * 128 + 4 * l, msg[0], msg[1], msg[2], msg[3]);
    }
}

// ---------------- h = relu(h + agg), float4 ----------------------------------
__global__ __launch_bounds__(256) void relu_add_kernel(float4* __restrict__ h, const float4* __restrict__ agg)
{
    int idx = blockIdx.x * 256 + threadIdx.x;
    float4 a = h[idx], b = agg[idx];
    a.x = fmaxf(a.x + b.x, 0.f);
    a.y = fmaxf(a.y + b.y, 0.f);
    a.z = fmaxf(a.z + b.z, 0.f);
    a.w = fmaxf(a.w + b.w, 0.f);
    h[idx] = a;
}

// ---------------- final relu + mean pool fused (vector RED) -------------------
__global__ __launch_bounds__(256) void relu_pool_kernel(
    const float4* __restrict__ h, const float4* __restrict__ agg,
    const int* __restrict__ batch,
    float* __restrict__ gsum, float* __restrict__ gcnt)
{
    int idx = blockIdx.x * 256 + threadIdx.x;    // (node, 4-channel group): 50000*32
    int n = idx >> 5, q = idx & 31;
    float4 a = h[idx], b = agg[idx];
    a.x = fmaxf(a.x + b.x, 0.f);
    a.y = fmaxf(a.y + b.y, 0.f);
    a.z = fmaxf(a.z + b.z, 0.f);
    a.w = fmaxf(a.w + b.w, 0.f);
    int g = batch[n];
    red_v4(gsum + (size_t)g * 128 + 4 * q, a.x, a.y, a.z, a.w);
    if (q == 0) atomicAdd(gcnt + g, 1.f);
}

// ---------------- final MLP ---------------------------------------------------
__global__ __launch_bounds__(128) void final_kernel(
    const float* __restrict__ gsum, const float* __restrict__ gcnt,
    const float* __restrict__ W1, const float* __restrict__ b1,
    const float* __restrict__ Wh, const float* __restrict__ bh,
    float* __restrict__ out)
{
    __shared__ float mean[128];
    __shared__ float ga[128];
    int g = blockIdx.x;
    int c = threadIdx.x;
    float cnt = fmaxf(gcnt[g], 1.f);
    mean[c] = gsum[(size_t)g * 128 + c] / cnt;
    __syncthreads();
    float acc = b1[c];
#pragma unroll 8
    for (int k = 0; k < 128; k++)
        acc += mean[k] * W1[k * 128 + c];
    ga[c] = fmaxf(acc, 0.f);
    __syncthreads();
    if (c < 5) {
        float o = bh[c];
#pragma unroll 8
        for (int k = 0; k < 128; k++)
            o += ga[k] * Wh[c * 128 + k];
        out[g * 5 + c] = o;
    }
}

// =============================================================================
extern "C" void kernel_launch(void* const* d_in, const int* in_sizes, int n_in,
                              void* d_out, int out_size)
{
    const float* x        = (const float*)d_in[0];
    const int*   eidx     = (const int*)  d_in[1];
    const float* eattr    = (const float*)d_in[2];
    const int*   batch    = (const int*)  d_in[3];
    const float* Wf1      = (const float*)d_in[4];
    const float* bf1      = (const float*)d_in[5];
    const float* Ws1      = (const float*)d_in[6];
    const float* bs1      = (const float*)d_in[7];
    const float* Wp       = (const float*)d_in[8];
    const float* bp       = (const float*)d_in[9];
    const float* Wf_convs = (const float*)d_in[10];
    const float* bf_convs = (const float*)d_in[11];
    const float* Ws_convs = (const float*)d_in[12];
    const float* bs_convs = (const float*)d_in[13];
    const float* W1       = (const float*)d_in[14];
    const float* b1       = (const float*)d_in[15];
    const float* Wh       = (const float*)d_in[16];
    const float* bh       = (const float*)d_in[17];
    float* out = (float*)d_out;

    const int* srcp = eidx;
    const int* dstp = eidx + N_EDGES;

    float *p_h, *p_agg, *p_WW, *p_gsum, *p_gcnt;
    __half *p_A, *p_WT;
    cudaGetSymbolAddress((void**)&p_h,    g_h);
    cudaGetSymbolAddress((void**)&p_agg,  g_agg);
    cudaGetSymbolAddress((void**)&p_A,    g_A);
    cudaGetSymbolAddress((void**)&p_WW,   g_WW);
    cudaGetSymbolAddress((void**)&p_WT,   g_WT);
    cudaGetSymbolAddress((void**)&p_gsum, g_gsum);
    cudaGetSymbolAddress((void**)&p_gcnt, g_gcnt);

    static int smem_cfg = 0;
    if (!smem_cfg) {
        cudaFuncSetAttribute(edge_kernel, cudaFuncAttributeMaxDynamicSharedMemorySize, 54272);
        smem_cfg = 1;
    }

    const int EB  = N_EDGES / 256;                    // 3125 (conv1)
    const int EB2 = N_EDGES / 64;                     // 12500 (fused edge)
    const int NB  = (N_NODES * HIDDEN) / 256;         // 25000
    const int NB4 = (N_NODES * HIDDEN / 4) / 256;     // 6250

    // conv1
    cudaMemsetAsync(p_agg, 0, (size_t)N_NODES * 3 * sizeof(float));
    conv1_kernel<<<EB, 256>>>(x, srcp, dstp, eattr, Wf1, bf1, Ws1, bs1, p_agg);
    proj_kernel<<<NB, 256>>>(x, p_agg, Wp, bp, p_h);

    cudaMemsetAsync(p_gsum, 0, (size_t)NUM_GRAPHS * HIDDEN * sizeof(float));
    cudaMemsetAsync(p_gcnt, 0, (size_t)NUM_GRAPHS * sizeof(float));

    // two big CGConv layers
    for (int l = 0; l < 2; l++) {
        const float* Wf = Wf_convs + (size_t)l * 288 * 128;
        const float* Ws = Ws_convs + (size_t)l * 288 * 128;
        const float* bf = bf_convs + (size_t)l * 128;
        const float* bs = bs_convs + (size_t)l * 128;

        pack_kernel<<<(128 * 512) / 256, 256>>>(Wf, Ws, p_WW, p_WT);
        dim3 gg((N_NODES + 127) / 128, 4);
        gemm_node<<<gg, 256>>>(p_h, p_WW, p_A);
        cudaMemsetAsync(p_agg, 0, (size_t)N_NODES * HIDDEN * sizeof(float));
        edge_kernel<<<EB2, 256, 54272>>>(srcp, dstp, eattr, p_WT, bf, bs,
                                         (const uint4*)p_A, p_agg);
        if (l == 0)
            relu_add_kernel<<<NB4, 256>>>((float4*)p_h, (const float4*)p_agg);
        else
            relu_pool_kernel<<<NB4, 256>>>((const float4*)p_h, (const float4*)p_agg,
                                           batch, p_gsum, p_gcnt);
    }

    final_kernel<<<NUM_GRAPHS, 128>>>(p_gsum, p_gcnt, W1, b1, Wh, bh, out);
}

// round 6
// speedup vs baseline: 1.3178x; 1.0148x over previous
#include <cuda_runtime.h>
#include <cuda_fp16.h>
#include <mma.h>
#include <math.h>

using namespace nvcuda;

#define N_NODES   50000
#define N_PAD     50048          // 391*128
#define N_EDGES   800000
#define HIDDEN    128
#define NUM_GRAPHS 256

// ---------------- scratch (device globals) ----------------------------------
__device__ float  g_h[N_NODES * HIDDEN];
__device__ float  g_hT[(size_t)HIDDEN * N_PAD];   // transposed h (25.6 MB)
__device__ float  g_agg[N_NODES * HIDDEN];
__device__ __half g_A[(size_t)N_NODES * 512];     // packed projections fp16 (51 MB)
__device__ float  g_WW[128 * 512];                // node GEMM weight fp32 (packed)
__device__ __half g_WT[256 * 32];                 // edge gate W^T fp16
__device__ float  g_gsum[NUM_GRAPHS * HIDDEN];
__device__ float  g_gcnt[NUM_GRAPHS];

// ---------------- helpers ------------------------------------------------------
__device__ __forceinline__ unsigned long long mk2(float lo, float hi) {
    unsigned long long r; asm("mov.b64 %0, {%1, %2};" : "=l"(r) : "f"(lo), "f"(hi)); return r;
}
__device__ __forceinline__ unsigned long long dup2(float x) {
    unsigned long long r; asm("mov.b64 %0, {%1, %1};" : "=l"(r) : "f"(x)); return r;
}
__device__ __forceinline__ void fma2(unsigned long long &d, unsigned long long a, unsigned long long b) {
    asm("fma.rn.f32x2 %0, %1, %2, %3;" : "=l"(d) : "l"(a), "l"(b), "l"(d));
}
__device__ __forceinline__ float2 unpk(unsigned long long v) {
    float2 r; asm("mov.b64 {%0, %1}, %2;" : "=f"(r.x), "=f"(r.y) : "l"(v)); return r;
}
__device__ __forceinline__ void red_v4(float* p, float a, float b, float c, float d) {
    asm volatile("red.global.add.v4.f32 [%0], {%1,%2,%3,%4};"
                 :: "l"(p), "f"(a), "f"(b), "f"(c), "f"(d) : "memory");
}
__device__ __forceinline__ unsigned smaddr(const void* p) {
    return (unsigned)__cvta_generic_to_shared(p);
}
#define CP16(dst, src) asm volatile("cp.async.cg.shared.global [%0], [%1], 16;" :: "r"(dst), "l"(src))
#define CP_COMMIT()    asm volatile("cp.async.commit_group;" ::: "memory")
#define CP_WAIT1()     asm volatile("cp.async.wait_group 1;" ::: "memory")
#define CP_WAIT0()     asm volatile("cp.async.wait_group 0;" ::: "memory")

// ---------------- conv1: CGConv(C=3, edge=32) -------------------------------
__global__ __launch_bounds__(256) void conv1_kernel(
    const float* __restrict__ x, const int* __restrict__ src, const int* __restrict__ dst,
    const float* __restrict__ eattr,
    const float* __restrict__ Wf, const float* __restrict__ bf,
    const float* __restrict__ Ws, const float* __restrict__ bs,
    float* __restrict__ agg)
{
    __shared__ float wf[38 * 3], ws[38 * 3], bfs[3], bss[3];
    int tid = threadIdx.x;
    if (tid < 114) { wf[tid] = Wf[tid]; ws[tid] = Ws[tid]; }
    if (tid < 3)   { bfs[tid] = bf[tid]; bss[tid] = bs[tid]; }
    __syncthreads();

    int e = blockIdx.x * 256 + tid;
    int d  = dst[e];
    int sn = src[e];

    float f[3], s[3];
#pragma unroll
    for (int j = 0; j < 3; j++) { f[j] = bfs[j]; s[j] = bss[j]; }

#pragma unroll
    for (int i = 0; i < 3; i++) {
        float xd = x[d * 3 + i];
        float xs = x[sn * 3 + i];
#pragma unroll
        for (int j = 0; j < 3; j++) {
            f[j] += xd * wf[i * 3 + j];
            s[j] += xd * ws[i * 3 + j];
            f[j] += xs * wf[(3 + i) * 3 + j];
            s[j] += xs * ws[(3 + i) * 3 + j];
        }
    }
    const float4* ep = (const float4*)(eattr + (size_t)e * 32);
#pragma unroll
    for (int q = 0; q < 8; q++) {
        float4 v = ep[q];
        float ev[4] = {v.x, v.y, v.z, v.w};
#pragma unroll
        for (int r = 0; r < 4; r++) {
            int k = 6 + q * 4 + r;
#pragma unroll
            for (int j = 0; j < 3; j++) {
                f[j] += ev[r] * wf[k * 3 + j];
                s[j] += ev[r] * ws[k * 3 + j];
            }
        }
    }
#pragma unroll
    for (int j = 0; j < 3; j++) {
        float sg = __fdividef(1.f, 1.f + __expf(-f[j]));
        float sp = fmaxf(s[j], 0.f) + __logf(1.f + __expf(-fabsf(s[j])));
        atomicAdd(agg + (size_t)d * 3 + j, sg * sp);
    }
}

// ---------------- node projection -------------------------------------------
__global__ __launch_bounds__(256) void proj_kernel(
    const float* __restrict__ x, const float* __restrict__ agg1,
    const float* __restrict__ Wp, const float* __restrict__ bp,
    float* __restrict__ h)
{
    int idx = blockIdx.x * 256 + threadIdx.x;
    int n = idx >> 7, c = idx & 127;
    float v = bp[c];
#pragma unroll
    for (int i = 0; i < 3; i++)
        v += (x[n * 3 + i] + agg1[n * 3 + i]) * Wp[i * 128 + c];
    h[idx] = fmaxf(v, 0.f);
}

// ---------------- transpose h -> hT[128][N_PAD] ------------------------------
__global__ __launch_bounds__(256) void transpose_kernel(
    const float* __restrict__ h, float* __restrict__ hT)
{
    __shared__ float t[32][33];
    int bn = blockIdx.x * 32;     // node base
    int bc = blockIdx.y * 32;     // channel base
    int tx = threadIdx.x & 31, ty = threadIdx.x >> 5;   // 32 x 8
#pragma unroll
    for (int j = 0; j < 32; j += 8) {
        int n = bn + ty + j;
        t[ty + j][tx] = (n < N_NODES) ? h[(size_t)n * 128 + bc + tx] : 0.f;
    }
    __syncthreads();
#pragma unroll
    for (int j = 0; j < 32; j += 8)
        hT[(size_t)(bc + ty + j) * N_PAD + bn + tx] = t[tx][ty + j];
}

// ---------------- weight pack: WW fp32 [128][512], WT fp16 [256][32] ---------
__global__ __launch_bounds__(256) void pack_kernel(
    const float* __restrict__ Wf, const float* __restrict__ Ws,
    float* __restrict__ WW, __half* __restrict__ WT)
{
    int idx = blockIdx.x * 256 + threadIdx.x;   // 0 .. 128*512-1
    {
        int k = idx >> 9;
        int j = idx & 511;
        int role = j >> 8;
        int c = (j & 255) >> 1;
        int gate = j & 1;
        const float* G = gate ? Ws : Wf;
        WW[idx] = G[(role * 128 + k) * 128 + c];
    }
    if (idx < 256 * 32) {
        int g = idx >> 5;
        int k = idx & 31;
        int c = g >> 1;
        int gate = g & 1;
        const float* G = gate ? Ws : Wf;
        WT[idx] = __float2half(G[(256 + k) * 128 + c]);
    }
}

// ---------------- node GEMM (cp.async double-buffered, f32x2) ----------------
// A[row,512](fp16) = h @ WW ; h comes in transposed as hT[128][N_PAD]
__global__ __launch_bounds__(256) void gemm_node(
    const float* __restrict__ HT, const float* __restrict__ W, __half* __restrict__ A)
{
    __shared__ float hs[2][16][132];
    __shared__ float ws[2][16][128];
    int tid = threadIdx.x;
    int bm = blockIdx.x * 128;
    int bn = blockIdx.y * 128;
    int tm = (tid >> 4) * 8;
    int tn = (tid & 15) * 8;

    unsigned long long acc2[8][4];
#pragma unroll
    for (int i = 0; i < 8; i++)
#pragma unroll
        for (int j = 0; j < 4; j++) acc2[i][j] = 0ULL;

    // staging: thread handles chunks tid and tid+256 of 512 (16 rows x 32 chunks)
    int k_a = tid >> 5,          m4_a = tid & 31;
    int k_b = (tid + 256) >> 5,  m4_b = tid & 31;

#define STAGE(buf, k0) do { \
        CP16(smaddr(&hs[buf][k_a][m4_a * 4]), HT + (size_t)((k0) + k_a) * N_PAD + bm + m4_a * 4); \
        CP16(smaddr(&ws[buf][k_a][m4_a * 4]), W  + (size_t)((k0) + k_a) * 512  + bn + m4_a * 4); \
        CP16(smaddr(&hs[buf][k_b][m4_b * 4]), HT + (size_t)((k0) + k_b) * N_PAD + bm + m4_b * 4); \
        CP16(smaddr(&ws[buf][k_b][m4_b * 4]), W  + (size_t)((k0) + k_b) * 512  + bn + m4_b * 4); \
    } while (0)

    STAGE(0, 0);
    CP_COMMIT();

#pragma unroll 1
    for (int c = 0; c < 8; c++) {
        int cur = c & 1;
        if (c < 7) {
            STAGE(cur ^ 1, (c + 1) * 16);
            CP_COMMIT();
            CP_WAIT1();
        } else {
            CP_WAIT0();
        }
        __syncthreads();
#pragma unroll
        for (int k = 0; k < 16; k++) {
            float4 a0 = *(float4*)&hs[cur][k][tm];
            float4 a1 = *(float4*)&hs[cur][k][tm + 4];
            float4 w0 = *(float4*)&ws[cur][k][tn];
            float4 w1 = *(float4*)&ws[cur][k][tn + 4];
            unsigned long long wp0 = mk2(w0.x, w0.y);
            unsigned long long wp1 = mk2(w0.z, w0.w);
            unsigned long long wp2 = mk2(w1.x, w1.y);
            unsigned long long wp3 = mk2(w1.z, w1.w);
            float am[8] = {a0.x, a0.y, a0.z, a0.w, a1.x, a1.y, a1.z, a1.w};
#pragma unroll
            for (int i = 0; i < 8; i++) {
                unsigned long long ad = dup2(am[i]);
                fma2(acc2[i][0], ad, wp0);
                fma2(acc2[i][1], ad, wp1);
                fma2(acc2[i][2], ad, wp2);
                fma2(acc2[i][3], ad, wp3);
            }
        }
        __syncthreads();
    }
#undef STAGE

#pragma unroll
    for (int i = 0; i < 8; i++) {
        int row = bm + tm + i;
        if (row < N_NODES) {
            uint4 o;
            unsigned* op = (unsigned*)&o;
#pragma unroll
            for (int p = 0; p < 4; p++) {
                float2 fp = unpk(acc2[i][p]);
                __half2 hp = __floats2half2_rn(fp.x, fp.y);
                op[p] = *(unsigned*)&hp;
            }
            *(uint4*)(A + (size_t)row * 512 + bn + tn) = o;
        }
    }
}

// ---------------- fused CGConv edge kernel (64 edges/block) ------------------
__global__ __launch_bounds__(256) void edge_kernel(
    const int* __restrict__ src, const int* __restrict__ dst,
    const float* __restrict__ eattr,
    const __half* __restrict__ WT,
    const float* __restrict__ bf, const float* __restrict__ bs,
    const uint4* __restrict__ A4, float* __restrict__ agg)
{
    extern __shared__ char sm[];
    __half (*Es)[32]   = (__half(*)[32])sm;                        // 4 KB
    __half (*WTs)[32]  = (__half(*)[32])(sm + 4096);               // 16 KB
    __half (*Ew)[256]  = (__half(*)[256])(sm + 4096 + 16384);      // 32 KB
    int2*  di          = (int2*)(sm + 4096 + 16384 + 32768);       // 512 B

    int tid = threadIdx.x;
    int w   = tid >> 5;
    int l   = tid & 31;
    int ebase = blockIdx.x * 64;

    if (tid < 64) di[tid] = make_int2(dst[ebase + tid], src[ebase + tid]);
    {   // edge attrs -> fp16 smem (streaming)
        const float4* b4 = (const float4*)(eattr + (size_t)ebase * 32);
#pragma unroll
        for (int t = 0; t < 2; t++) {
            int li = tid + t * 256;        // 0..511
            float4 v = __ldcs(b4 + li);
            int e = li >> 3, q = li & 7;
            __half2* dp = (__half2*)&Es[e][q * 4];
            dp[0] = __floats2half2_rn(v.x, v.y);
            dp[1] = __floats2half2_rn(v.z, v.w);
        }
    }
    {   // gate weights
        const uint4* wsrc = (const uint4*)WT;
        uint4* wdst = (uint4*)WTs;
#pragma unroll
        for (int t = 0; t < 4; t++)
            wdst[tid + t * 256] = wsrc[tid + t * 256];
    }
    __syncthreads();

    // phase 1: Ew[64][256] = Es @ WT^T  (wmma, fp32 accum)
    {
        int mt = w & 3;
        int nb = (w >> 2) * 8;
        wmma::fragment<wmma::matrix_a, 16, 16, 16, __half, wmma::row_major> a0, a1;
        wmma::load_matrix_sync(a0, &Es[mt * 16][0], 32);
        wmma::load_matrix_sync(a1, &Es[mt * 16][16], 32);
#pragma unroll
        for (int t = 0; t < 8; t++) {
            int nt = nb + t;
            wmma::fragment<wmma::accumulator, 16, 16, 16, float> acc;
            wmma::fill_fragment(acc, 0.f);
            wmma::fragment<wmma::matrix_b, 16, 16, 16, __half, wmma::col_major> b0, b1;
            wmma::load_matrix_sync(b0, &WTs[nt * 16][0], 32);
            wmma::load_matrix_sync(b1, &WTs[nt * 16][16], 32);
            wmma::mma_sync(acc, a0, b0, acc);
            wmma::mma_sync(acc, a1, b1, acc);
            wmma::fragment<wmma::accumulator, 16, 16, 16, __half> hacc;
#pragma unroll
            for (int i = 0; i < acc.num_elements; i++) hacc.x[i] = __float2half(acc.x[i]);
            wmma::store_matrix_sync(&Ew[mt * 16][nt * 16], hacc, 256, wmma::mem_row_major);
        }
    }
    __syncthreads();

    // phase 2: warp-per-edge, lane l owns channels 4l..4l+3, PF=4 pipeline
    float4 bf4 = *(const float4*)(bf + 4 * l);
    float4 bs4 = *(const float4*)(bs + 4 * l);
    int e0 = w * 8;

    int   dsd[4];
    uint4 pd[4], ps[4];
#pragma unroll
    for (int i = 0; i < 4; i++) {
        int2 ds = di[e0 + i];
        dsd[i] = ds.x;
        pd[i] = __ldg(A4 + (size_t)ds.x * 64 + l);
        ps[i] = __ldg(A4 + (size_t)ds.y * 64 + 32 + l);
    }

#pragma unroll
    for (int i = 0; i < 8; i++) {
        int b = i & 3;
        uint4 rd = pd[b], rs = ps[b];
        int dcur = dsd[b];
        if (i < 4) {
            int2 ds = di[e0 + i + 4];
            dsd[b] = ds.x;
            pd[b] = __ldg(A4 + (size_t)ds.x * 64 + l);
            ps[b] = __ldg(A4 + (size_t)ds.y * 64 + 32 + l);
        }
        uint4 ewv = *(uint4*)&Ew[e0 + i][8 * l];
        const __half2* hd  = (const __half2*)&rd;
        const __half2* hsv = (const __half2*)&rs;
        const __half2* he  = (const __half2*)&ewv;
        const float* bfp = (const float*)&bf4;
        const float* bsp = (const float*)&bs4;
        float msg[4];
#pragma unroll
        for (int j = 0; j < 4; j++) {
            float2 fd = __half22float2(hd[j]);
            float2 fv = __half22float2(hsv[j]);
            float2 fe = __half22float2(he[j]);
            float f = bfp[j] + fd.x + fv.x + fe.x;
            float s = bsp[j] + fd.y + fv.y + fe.y;
            float sg = __fdividef(1.f, 1.f + __expf(-f));
            float sp = fmaxf(s, 0.f) + __logf(1.f + __expf(-fabsf(s)));
            msg[j] = sg * sp;
        }
        red_v4(agg + (size_t)dcur * 128 + 4 * l, msg[0], msg[1], msg[2], msg[3]);
    }
}

// ---------------- h = relu(h + agg), float4 ----------------------------------
__global__ __launch_bounds__(256) void relu_add_kernel(float4* __restrict__ h, const float4* __restrict__ agg)
{
    int idx = blockIdx.x * 256 + threadIdx.x;
    float4 a = h[idx], b = agg[idx];
    a.x = fmaxf(a.x + b.x, 0.f);
    a.y = fmaxf(a.y + b.y, 0.f);
    a.z = fmaxf(a.z + b.z, 0.f);
    a.w = fmaxf(a.w + b.w, 0.f);
    h[idx] = a;
}

// ---------------- final relu + mean pool fused (vector RED) -------------------
__global__ __launch_bounds__(256) void relu_pool_kernel(
    const float4* __restrict__ h, const float4* __restrict__ agg,
    const int* __restrict__ batch,
    float* __restrict__ gsum, float* __restrict__ gcnt)
{
    int idx = blockIdx.x * 256 + threadIdx.x;    // (node, 4-channel group): 50000*32
    int n = idx >> 5, q = idx & 31;
    float4 a = h[idx], b = agg[idx];
    a.x = fmaxf(a.x + b.x, 0.f);
    a.y = fmaxf(a.y + b.y, 0.f);
    a.z = fmaxf(a.z + b.z, 0.f);
    a.w = fmaxf(a.w + b.w, 0.f);
    int g = batch[n];
    red_v4(gsum + (size_t)g * 128 + 4 * q, a.x, a.y, a.z, a.w);
    if (q == 0) atomicAdd(gcnt + g, 1.f);
}

// ---------------- final MLP ---------------------------------------------------
__global__ __launch_bounds__(128) void final_kernel(
    const float* __restrict__ gsum, const float* __restrict__ gcnt,
    const float* __restrict__ W1, const float* __restrict__ b1,
    const float* __restrict__ Wh, const float* __restrict__ bh,
    float* __restrict__ out)
{
    __shared__ float mean[128];
    __shared__ float ga[128];
    int g = blockIdx.x;
    int c = threadIdx.x;
    float cnt = fmaxf(gcnt[g], 1.f);
    mean[c] = gsum[(size_t)g * 128 + c] / cnt;
    __syncthreads();
    float acc = b1[c];
#pragma unroll 8
    for (int k = 0; k < 128; k++)
        acc += mean[k] * W1[k * 128 + c];
    ga[c] = fmaxf(acc, 0.f);
    __syncthreads();
    if (c < 5) {
        float o = bh[c];
#pragma unroll 8
        for (int k = 0; k < 128; k++)
            o += ga[k] * Wh[c * 128 + k];
        out[g * 5 + c] = o;
    }
}

// =============================================================================
extern "C" void kernel_launch(void* const* d_in, const int* in_sizes, int n_in,
                              void* d_out, int out_size)
{
    const float* x        = (const float*)d_in[0];
    const int*   eidx     = (const int*)  d_in[1];
    const float* eattr    = (const float*)d_in[2];
    const int*   batch    = (const int*)  d_in[3];
    const float* Wf1      = (const float*)d_in[4];
    const float* bf1      = (const float*)d_in[5];
    const float* Ws1      = (const float*)d_in[6];
    const float* bs1      = (const float*)d_in[7];
    const float* Wp       = (const float*)d_in[8];
    const float* bp       = (const float*)d_in[9];
    const float* Wf_convs = (const float*)d_in[10];
    const float* bf_convs = (const float*)d_in[11];
    const float* Ws_convs = (const float*)d_in[12];
    const float* bs_convs = (const float*)d_in[13];
    const float* W1       = (const float*)d_in[14];
    const float* b1       = (const float*)d_in[15];
    const float* Wh       = (const float*)d_in[16];
    const float* bh       = (const float*)d_in[17];
    float* out = (float*)d_out;

    const int* srcp = eidx;
    const int* dstp = eidx + N_EDGES;

    float *p_h, *p_hT, *p_agg, *p_WW, *p_gsum, *p_gcnt;
    __half *p_A, *p_WT;
    cudaGetSymbolAddress((void**)&p_h,    g_h);
    cudaGetSymbolAddress((void**)&p_hT,   g_hT);
    cudaGetSymbolAddress((void**)&p_agg,  g_agg);
    cudaGetSymbolAddress((void**)&p_A,    g_A);
    cudaGetSymbolAddress((void**)&p_WW,   g_WW);
    cudaGetSymbolAddress((void**)&p_WT,   g_WT);
    cudaGetSymbolAddress((void**)&p_gsum, g_gsum);
    cudaGetSymbolAddress((void**)&p_gcnt, g_gcnt);

    static int smem_cfg = 0;
    if (!smem_cfg) {
        cudaFuncSetAttribute(edge_kernel, cudaFuncAttributeMaxDynamicSharedMemorySize, 54272);
        smem_cfg = 1;
    }

    const int EB  = N_EDGES / 256;                    // 3125 (conv1)
    const int EB2 = N_EDGES / 64;                     // 12500 (fused edge)
    const int NB  = (N_NODES * HIDDEN) / 256;         // 25000
    const int NB4 = (N_NODES * HIDDEN / 4) / 256;     // 6250
    dim3 tg(N_PAD / 32, 4);                           // transpose grid

    // conv1
    cudaMemsetAsync(p_agg, 0, (size_t)N_NODES * 3 * sizeof(float));
    conv1_kernel<<<EB, 256>>>(x, srcp, dstp, eattr, Wf1, bf1, Ws1, bs1, p_agg);
    proj_kernel<<<NB, 256>>>(x, p_agg, Wp, bp, p_h);

    cudaMemsetAsync(p_gsum, 0, (size_t)NUM_GRAPHS * HIDDEN * sizeof(float));
    cudaMemsetAsync(p_gcnt, 0, (size_t)NUM_GRAPHS * sizeof(float));

    // two big CGConv layers
    for (int l = 0; l < 2; l++) {
        const float* Wf = Wf_convs + (size_t)l * 288 * 128;
        const float* Ws = Ws_convs + (size_t)l * 288 * 128;
        const float* bf = bf_convs + (size_t)l * 128;
        const float* bs = bs_convs + (size_t)l * 128;

        transpose_kernel<<<tg, 256>>>(p_h, p_hT);
        pack_kernel<<<(128 * 512) / 256, 256>>>(Wf, Ws, p_WW, p_WT);
        dim3 gg(N_PAD / 128, 4);
        gemm_node<<<gg, 256>>>(p_hT, p_WW, p_A);
        cudaMemsetAsync(p_agg, 0, (size_t)N_NODES * HIDDEN * sizeof(float));
        edge_kernel<<<EB2, 256, 54272>>>(srcp, dstp, eattr, p_WT, bf, bs,
                                         (const uint4*)p_A, p_agg);
        if (l == 0)
            relu_add_kernel<<<NB4, 256>>>((float4*)p_h, (const float4*)p_agg);
        else
            relu_pool_kernel<<<NB4, 256>>>((const float4*)p_h, (const float4*)p_agg,
                                           batch, p_gsum, p_gcnt);
    }

    final_kernel<<<NUM_GRAPHS, 128>>>(p_gsum, p_gcnt, W1, b1, Wh, bh, out);
}

// round 7
// speedup vs baseline: 1.4872x; 1.1286x over previous
#include <cuda_runtime.h>
#include <cuda_fp16.h>
#include <mma.h>
#include <math.h>

using namespace nvcuda;

#define N_NODES   50000
#define N_PAD     50048          // 391*128
#define N_EDGES   800000
#define HIDDEN    128
#define NUM_GRAPHS 256
#define GPAD      136            // padded smem row (halfs)

// ---------------- scratch (device globals) ----------------------------------
__device__ float  g_h[N_NODES * HIDDEN];
__device__ float  g_agg[N_NODES * HIDDEN];
__device__ __half g_hhi[N_NODES * HIDDEN];        // split h (12.8 MB each)
__device__ __half g_hlo[N_NODES * HIDDEN];
__device__ __half g_A[(size_t)N_PAD * 512];       // packed projections fp16
__device__ __half g_Whi[128 * 512];               // split packed node weight
__device__ __half g_Wlo[128 * 512];
__device__ __half g_WT[256 * 32];                 // edge gate W^T fp16
__device__ float  g_gsum[NUM_GRAPHS * HIDDEN];
__device__ float  g_gcnt[NUM_GRAPHS];

// ---------------- helpers ------------------------------------------------------
__device__ __forceinline__ void red_v4(float* p, float a, float b, float c, float d) {
    asm volatile("red.global.add.v4.f32 [%0], {%1,%2,%3,%4};"
                 :: "l"(p), "f"(a), "f"(b), "f"(c), "f"(d) : "memory");
}
__device__ __forceinline__ float tanh_fast(float x) {
    float r; asm("tanh.approx.f32 %0, %1;" : "=f"(r) : "f"(x)); return r;
}
__device__ __forceinline__ unsigned smaddr(const void* p) {
    return (unsigned)__cvta_generic_to_shared(p);
}
#define CP16(dst, src) asm volatile("cp.async.cg.shared.global [%0], [%1], 16;" :: "r"(dst), "l"(src))
#define CP_COMMIT()    asm volatile("cp.async.commit_group;" ::: "memory")
#define CP_WAIT0()     asm volatile("cp.async.wait_group 0;" ::: "memory")

// ---------------- conv1: CGConv(C=3, edge=32) -------------------------------
__global__ __launch_bounds__(256) void conv1_kernel(
    const float* __restrict__ x, const int* __restrict__ src, const int* __restrict__ dst,
    const float* __restrict__ eattr,
    const float* __restrict__ Wf, const float* __restrict__ bf,
    const float* __restrict__ Ws, const float* __restrict__ bs,
    float* __restrict__ agg)
{
    __shared__ float wf[38 * 3], ws[38 * 3], bfs[3], bss[3];
    int tid = threadIdx.x;
    if (tid < 114) { wf[tid] = Wf[tid]; ws[tid] = Ws[tid]; }
    if (tid < 3)   { bfs[tid] = bf[tid]; bss[tid] = bs[tid]; }
    __syncthreads();

    int e = blockIdx.x * 256 + tid;
    int d  = dst[e];
    int sn = src[e];

    float f[3], s[3];
#pragma unroll
    for (int j = 0; j < 3; j++) { f[j] = bfs[j]; s[j] = bss[j]; }

#pragma unroll
    for (int i = 0; i < 3; i++) {
        float xd = x[d * 3 + i];
        float xs = x[sn * 3 + i];
#pragma unroll
        for (int j = 0; j < 3; j++) {
            f[j] += xd * wf[i * 3 + j];
            s[j] += xd * ws[i * 3 + j];
            f[j] += xs * wf[(3 + i) * 3 + j];
            s[j] += xs * ws[(3 + i) * 3 + j];
        }
    }
    const float4* ep = (const float4*)(eattr + (size_t)e * 32);
#pragma unroll
    for (int q = 0; q < 8; q++) {
        float4 v = ep[q];
        float ev[4] = {v.x, v.y, v.z, v.w};
#pragma unroll
        for (int r = 0; r < 4; r++) {
            int k = 6 + q * 4 + r;
#pragma unroll
            for (int j = 0; j < 3; j++) {
                f[j] += ev[r] * wf[k * 3 + j];
                s[j] += ev[r] * ws[k * 3 + j];
            }
        }
    }
#pragma unroll
    for (int j = 0; j < 3; j++) {
        float sg = 0.5f + 0.5f * tanh_fast(0.5f * f[j]);
        float sp = fmaxf(s[j], 0.f) + __logf(1.f + __expf(-fabsf(s[j])));
        atomicAdd(agg + (size_t)d * 3 + j, sg * sp);
    }
}

// ---------------- node projection -------------------------------------------
__global__ __launch_bounds__(256) void proj_kernel(
    const float* __restrict__ x, const float* __restrict__ agg1,
    const float* __restrict__ Wp, const float* __restrict__ bp,
    float* __restrict__ h)
{
    int idx = blockIdx.x * 256 + threadIdx.x;
    int n = idx >> 7, c = idx & 127;
    float v = bp[c];
#pragma unroll
    for (int i = 0; i < 3; i++)
        v += (x[n * 3 + i] + agg1[n * 3 + i]) * Wp[i * 128 + c];
    h[idx] = fmaxf(v, 0.f);
}

// ---------------- h split: fp32 -> (hi fp16, lo fp16 residual) ----------------
__global__ __launch_bounds__(256) void h2split_kernel(
    const float4* __restrict__ h, __half2* __restrict__ hhi, __half2* __restrict__ hlo)
{
    int idx = blockIdx.x * 256 + threadIdx.x;      // 1.6M float4
    float4 v = h[idx];
    __half hx = __float2half(v.x), hy = __float2half(v.y);
    __half hz = __float2half(v.z), hw = __float2half(v.w);
    __half lx = __float2half(v.x - __half2float(hx));
    __half ly = __float2half(v.y - __half2float(hy));
    __half lz = __float2half(v.z - __half2float(hz));
    __half lw = __float2half(v.w - __half2float(hw));
    hhi[idx * 2 + 0] = __halves2half2(hx, hy);
    hhi[idx * 2 + 1] = __halves2half2(hz, hw);
    hlo[idx * 2 + 0] = __halves2half2(lx, ly);
    hlo[idx * 2 + 1] = __halves2half2(lz, lw);
}

// ---------------- weight pack: split Whi/Wlo [128][512], WT fp16 [256][32] ---
__global__ __launch_bounds__(256) void pack_kernel(
    const float* __restrict__ Wf, const float* __restrict__ Ws,
    __half* __restrict__ Whi, __half* __restrict__ Wlo, __half* __restrict__ WT)
{
    int idx = blockIdx.x * 256 + threadIdx.x;   // 0 .. 128*512-1
    {
        int k = idx >> 9;
        int j = idx & 511;
        int role = j >> 8;
        int c = (j & 255) >> 1;
        int gate = j & 1;
        const float* G = gate ? Ws : Wf;
        float v = G[(role * 128 + k) * 128 + c];
        __half hi = __float2half(v);
        Whi[idx] = hi;
        Wlo[idx] = __float2half(v - __half2float(hi));
    }
    if (idx < 256 * 32) {
        int g = idx >> 5;
        int k = idx & 31;
        int c = g >> 1;
        int gate = g & 1;
        const float* G = gate ? Ws : Wf;
        WT[idx] = __float2half(G[(256 + k) * 128 + c]);
    }
}

// ---------------- node GEMM via split-fp16 wmma ------------------------------
// A[row, 512](fp16) = h @ W,  error ~ fp32 (hi*hi + hi*lo + lo*hi)
__global__ __launch_bounds__(512) void gemm_node(
    const __half* __restrict__ Hhi, const __half* __restrict__ Hlo,
    const __half* __restrict__ Whi, const __half* __restrict__ Wlo,
    __half* __restrict__ A)
{
    extern __shared__ __half sm[];
    __half (*hh)[GPAD] = (__half(*)[GPAD])sm;
    __half (*hl)[GPAD] = hh + 128;
    __half (*wh)[GPAD] = hl + 128;
    __half (*wl)[GPAD] = wh + 128;

    int tid = threadIdx.x;
    int bm = blockIdx.x * 128;
    int bn = blockIdx.y * 128;

    // stage all tiles (cp.async, single stage, whole K)
#pragma unroll
    for (int t = 0; t < 4; t++) {
        int li = tid + t * 512;          // 0..2047
        int row = li >> 4, q = li & 15;  // 128 rows x 16 uint4
        int rg = bm + row; if (rg > N_NODES - 1) rg = N_NODES - 1;
        CP16(smaddr(&hh[row][q * 8]), Hhi + (size_t)rg * 128 + q * 8);
        CP16(smaddr(&hl[row][q * 8]), Hlo + (size_t)rg * 128 + q * 8);
        CP16(smaddr(&wh[row][q * 8]), Whi + (size_t)row * 512 + bn + q * 8);
        CP16(smaddr(&wl[row][q * 8]), Wlo + (size_t)row * 512 + bn + q * 8);
    }
    CP_COMMIT();
    CP_WAIT0();
    __syncthreads();

    int w  = tid >> 5;
    int mw = w & 7;          // m-strip
    int nh = w >> 3;         // n-half (0/1)
    int m0 = mw * 16;

#pragma unroll
    for (int t = 0; t < 4; t++) {
        int n0 = (nh * 4 + t) * 16;
        wmma::fragment<wmma::accumulator, 16, 16, 16, float> acc;
        wmma::fill_fragment(acc, 0.f);
#pragma unroll
        for (int k = 0; k < 8; k++) {
            wmma::fragment<wmma::matrix_a, 16, 16, 16, __half, wmma::row_major> ah, al;
            wmma::fragment<wmma::matrix_b, 16, 16, 16, __half, wmma::row_major> bh, bl;
            wmma::load_matrix_sync(ah, &hh[m0][k * 16], GPAD);
            wmma::load_matrix_sync(al, &hl[m0][k * 16], GPAD);
            wmma::load_matrix_sync(bh, &wh[k * 16][n0], GPAD);
            wmma::load_matrix_sync(bl, &wl[k * 16][n0], GPAD);
            wmma::mma_sync(acc, ah, bh, acc);
            wmma::mma_sync(acc, ah, bl, acc);
            wmma::mma_sync(acc, al, bh, acc);
        }
        wmma::fragment<wmma::accumulator, 16, 16, 16, __half> hacc;
#pragma unroll
        for (int i = 0; i < acc.num_elements; i++) hacc.x[i] = __float2half(acc.x[i]);
        wmma::store_matrix_sync(A + (size_t)(bm + m0) * 512 + bn + n0,
                                hacc, 512, wmma::mem_row_major);
    }
}

// ---------------- fused CGConv edge kernel (64 edges/block) ------------------
__global__ __launch_bounds__(256) void edge_kernel(
    const int* __restrict__ src, const int* __restrict__ dst,
    const float* __restrict__ eattr,
    const __half* __restrict__ WT,
    const float* __restrict__ bf, const float* __restrict__ bs,
    const uint4* __restrict__ A4, float* __restrict__ agg)
{
    extern __shared__ char smc[];
    __half (*Es)[32]   = (__half(*)[32])smc;                        // 4 KB
    __half (*WTs)[32]  = (__half(*)[32])(smc + 4096);               // 16 KB
    __half (*Ew)[256]  = (__half(*)[256])(smc + 4096 + 16384);      // 32 KB
    int2*  di          = (int2*)(smc + 4096 + 16384 + 32768);       // 512 B

    int tid = threadIdx.x;
    int w   = tid >> 5;
    int l   = tid & 31;
    int ebase = blockIdx.x * 64;

    if (tid < 64) di[tid] = make_int2(dst[ebase + tid], src[ebase + tid]);
    {   // edge attrs -> fp16 smem (streaming)
        const float4* b4 = (const float4*)(eattr + (size_t)ebase * 32);
#pragma unroll
        for (int t = 0; t < 2; t++) {
            int li = tid + t * 256;        // 0..511
            float4 v = __ldcs(b4 + li);
            int e = li >> 3, q = li & 7;
            __half2* dp = (__half2*)&Es[e][q * 4];
            dp[0] = __floats2half2_rn(v.x, v.y);
            dp[1] = __floats2half2_rn(v.z, v.w);
        }
    }
    {   // gate weights
        const uint4* wsrc = (const uint4*)WT;
        uint4* wdst = (uint4*)WTs;
#pragma unroll
        for (int t = 0; t < 4; t++)
            wdst[tid + t * 256] = wsrc[tid + t * 256];
    }
    __syncthreads();

    // phase 1: Ew[64][256] = Es @ WT^T  (wmma, fp32 accum)
    {
        int mt = w & 3;
        int nb = (w >> 2) * 8;
        wmma::fragment<wmma::matrix_a, 16, 16, 16, __half, wmma::row_major> a0, a1;
        wmma::load_matrix_sync(a0, &Es[mt * 16][0], 32);
        wmma::load_matrix_sync(a1, &Es[mt * 16][16], 32);
#pragma unroll
        for (int t = 0; t < 8; t++) {
            int nt = nb + t;
            wmma::fragment<wmma::accumulator, 16, 16, 16, float> acc;
            wmma::fill_fragment(acc, 0.f);
            wmma::fragment<wmma::matrix_b, 16, 16, 16, __half, wmma::col_major> b0, b1;
            wmma::load_matrix_sync(b0, &WTs[nt * 16][0], 32);
            wmma::load_matrix_sync(b1, &WTs[nt * 16][16], 32);
            wmma::mma_sync(acc, a0, b0, acc);
            wmma::mma_sync(acc, a1, b1, acc);
            wmma::fragment<wmma::accumulator, 16, 16, 16, __half> hacc;
#pragma unroll
            for (int i = 0; i < acc.num_elements; i++) hacc.x[i] = __float2half(acc.x[i]);
            wmma::store_matrix_sync(&Ew[mt * 16][nt * 16], hacc, 256, wmma::mem_row_major);
        }
    }
    __syncthreads();

    // phase 2: warp-per-edge, lane l owns channels 4l..4l+3, PF=4 pipeline
    float4 bf4 = *(const float4*)(bf + 4 * l);
    float4 bs4 = *(const float4*)(bs + 4 * l);
    int e0 = w * 8;

    int   dsd[4];
    uint4 pd[4], ps[4];
#pragma unroll
    for (int i = 0; i < 4; i++) {
        int2 ds = di[e0 + i];
        dsd[i] = ds.x;
        pd[i] = __ldg(A4 + (size_t)ds.x * 64 + l);
        ps[i] = __ldg(A4 + (size_t)ds.y * 64 + 32 + l);
    }

#pragma unroll
    for (int i = 0; i < 8; i++) {
        int b = i & 3;
        uint4 rd = pd[b], rs = ps[b];
        int dcur = dsd[b];
        if (i < 4) {
            int2 ds = di[e0 + i + 4];
            dsd[b] = ds.x;
            pd[b] = __ldg(A4 + (size_t)ds.x * 64 + l);
            ps[b] = __ldg(A4 + (size_t)ds.y * 64 + 32 + l);
        }
        uint4 ewv = *(uint4*)&Ew[e0 + i][8 * l];
        const __half2* hd  = (const __half2*)&rd;
        const __half2* hsv = (const __half2*)&rs;
        const __half2* he  = (const __half2*)&ewv;
        const float* bfp = (const float*)&bf4;
        const float* bsp = (const float*)&bs4;
        float msg[4];
#pragma unroll
        for (int j = 0; j < 4; j++) {
            float2 fd = __half22float2(hd[j]);
            float2 fv = __half22float2(hsv[j]);
            float2 fe = __half22float2(he[j]);
            float f = bfp[j] + fd.x + fv.x + fe.x;
            float s = bsp[j] + fd.y + fv.y + fe.y;
            float sg = 0.5f + 0.5f * tanh_fast(0.5f * f);
            float sp = fmaxf(s, 0.f) + __logf(1.f + __expf(-fabsf(s)));
            msg[j] = sg * sp;
        }
        red_v4(agg + (size_t)dcur * 128 + 4 * l, msg[0], msg[1], msg[2], msg[3]);
    }
}

// ---------------- h = relu(h + agg), float4 ----------------------------------
__global__ __launch_bounds__(256) void relu_add_kernel(float4* __restrict__ h, const float4* __restrict__ agg)
{
    int idx = blockIdx.x * 256 + threadIdx.x;
    float4 a = h[idx], b = agg[idx];
    a.x = fmaxf(a.x + b.x, 0.f);
    a.y = fmaxf(a.y + b.y, 0.f);
    a.z = fmaxf(a.z + b.z, 0.f);
    a.w = fmaxf(a.w + b.w, 0.f);
    h[idx] = a;
}

// ---------------- final relu + mean pool fused (vector RED) -------------------
__global__ __launch_bounds__(256) void relu_pool_kernel(
    const float4* __restrict__ h, const float4* __restrict__ agg,
    const int* __restrict__ batch,
    float* __restrict__ gsum, float* __restrict__ gcnt)
{
    int idx = blockIdx.x * 256 + threadIdx.x;    // (node, 4-channel group): 50000*32
    int n = idx >> 5, q = idx & 31;
    float4 a = h[idx], b = agg[idx];
    a.x = fmaxf(a.x + b.x, 0.f);
    a.y = fmaxf(a.y + b.y, 0.f);
    a.z = fmaxf(a.z + b.z, 0.f);
    a.w = fmaxf(a.w + b.w, 0.f);
    int g = batch[n];
    red_v4(gsum + (size_t)g * 128 + 4 * q, a.x, a.y, a.z, a.w);
    if (q == 0) atomicAdd(gcnt + g, 1.f);
}

// ---------------- final MLP ---------------------------------------------------
__global__ __launch_bounds__(128) void final_kernel(
    const float* __restrict__ gsum, const float* __restrict__ gcnt,
    const float* __restrict__ W1, const float* __restrict__ b1,
    const float* __restrict__ Wh, const float* __restrict__ bh,
    float* __restrict__ out)
{
    __shared__ float mean[128];
    __shared__ float ga[128];
    int g = blockIdx.x;
    int c = threadIdx.x;
    float cnt = fmaxf(gcnt[g], 1.f);
    mean[c] = gsum[(size_t)g * 128 + c] / cnt;
    __syncthreads();
    float acc = b1[c];
#pragma unroll 8
    for (int k = 0; k < 128; k++)
        acc += mean[k] * W1[k * 128 + c];
    ga[c] = fmaxf(acc, 0.f);
    __syncthreads();
    if (c < 5) {
        float o = bh[c];
#pragma unroll 8
        for (int k = 0; k < 128; k++)
            o += ga[k] * Wh[c * 128 + k];
        out[g * 5 + c] = o;
    }
}

// =============================================================================
extern "C" void kernel_launch(void* const* d_in, const int* in_sizes, int n_in,
                              void* d_out, int out_size)
{
    const float* x        = (const float*)d_in[0];
    const int*   eidx     = (const int*)  d_in[1];
    const float* eattr    = (const float*)d_in[2];
    const int*   batch    = (const int*)  d_in[3];
    const float* Wf1      = (const float*)d_in[4];
    const float* bf1      = (const float*)d_in[5];
    const float* Ws1      = (const float*)d_in[6];
    const float* bs1      = (const float*)d_in[7];
    const float* Wp       = (const float*)d_in[8];
    const float* bp       = (const float*)d_in[9];
    const float* Wf_convs = (const float*)d_in[10];
    const float* bf_convs = (const float*)d_in[11];
    const float* Ws_convs = (const float*)d_in[12];
    const float* bs_convs = (const float*)d_in[13];
    const float* W1       = (const float*)d_in[14];
    const float* b1       = (const float*)d_in[15];
    const float* Wh       = (const float*)d_in[16];
    const float* bh       = (const float*)d_in[17];
    float* out = (float*)d_out;

    const int* srcp = eidx;
    const int* dstp = eidx + N_EDGES;

    float *p_h, *p_agg, *p_gsum, *p_gcnt;
    __half *p_hhi, *p_hlo, *p_A, *p_Whi, *p_Wlo, *p_WT;
    cudaGetSymbolAddress((void**)&p_h,    g_h);
    cudaGetSymbolAddress((void**)&p_agg,  g_agg);
    cudaGetSymbolAddress((void**)&p_hhi,  g_hhi);
    cudaGetSymbolAddress((void**)&p_hlo,  g_hlo);
    cudaGetSymbolAddress((void**)&p_A,    g_A);
    cudaGetSymbolAddress((void**)&p_Whi,  g_Whi);
    cudaGetSymbolAddress((void**)&p_Wlo,  g_Wlo);
    cudaGetSymbolAddress((void**)&p_WT,   g_WT);
    cudaGetSymbolAddress((void**)&p_gsum, g_gsum);
    cudaGetSymbolAddress((void**)&p_gcnt, g_gcnt);

    static int smem_cfg = 0;
    if (!smem_cfg) {
        cudaFuncSetAttribute(edge_kernel, cudaFuncAttributeMaxDynamicSharedMemorySize, 54272);
        cudaFuncSetAttribute(gemm_node, cudaFuncAttributeMaxDynamicSharedMemorySize, 4 * 128 * GPAD * 2);
        smem_cfg = 1;
    }

    const int EB  = N_EDGES / 256;                    // 3125 (conv1)
    const int EB2 = N_EDGES / 64;                     // 12500 (fused edge)
    const int NB  = (N_NODES * HIDDEN) / 256;         // 25000
    const int NB4 = (N_NODES * HIDDEN / 4) / 256;     // 6250

    // conv1
    cudaMemsetAsync(p_agg, 0, (size_t)N_NODES * 3 * sizeof(float));
    conv1_kernel<<<EB, 256>>>(x, srcp, dstp, eattr, Wf1, bf1, Ws1, bs1, p_agg);
    proj_kernel<<<NB, 256>>>(x, p_agg, Wp, bp, p_h);

    cudaMemsetAsync(p_gsum, 0, (size_t)NUM_GRAPHS * HIDDEN * sizeof(float));
    cudaMemsetAsync(p_gcnt, 0, (size_t)NUM_GRAPHS * sizeof(float));

    // two big CGConv layers
    for (int l = 0; l < 2; l++) {
        const float* Wf = Wf_convs + (size_t)l * 288 * 128;
        const float* Ws = Ws_convs + (size_t)l * 288 * 128;
        const float* bf = bf_convs + (size_t)l * 128;
        const float* bs = bs_convs + (size_t)l * 128;

        h2split_kernel<<<NB4, 256>>>((const float4*)p_h, (__half2*)p_hhi, (__half2*)p_hlo);
        pack_kernel<<<(128 * 512) / 256, 256>>>(Wf, Ws, p_Whi, p_Wlo, p_WT);
        dim3 gg(N_PAD / 128, 4);
        gemm_node<<<gg, 512, 4 * 128 * GPAD * 2>>>(p_hhi, p_hlo, p_Whi, p_Wlo, p_A);
        cudaMemsetAsync(p_agg, 0, (size_t)N_NODES * HIDDEN * sizeof(float));
        edge_kernel<<<EB2, 256, 54272>>>(srcp, dstp, eattr, p_WT, bf, bs,
                                         (const uint4*)p_A, p_agg);
        if (l == 0)
            relu_add_kernel<<<NB4, 256>>>((float4*)p_h, (const float4*)p_agg);
        else
            relu_pool_kernel<<<NB4, 256>>>((const float4*)p_h, (const float4*)p_agg,
                                           batch, p_gsum, p_gcnt);
    }

    final_kernel<<<NUM_GRAPHS, 128>>>(p_gsum, p_gcnt, W1, b1, Wh, bh, out);
}